// round 4
// baseline (speedup 1.0000x reference)
#include <cuda_runtime.h>
#include <math.h>

#define BB 4
#define NN 2048
#define MM 2048

// ---- persistent scratch (device globals; no allocation allowed) ----
__device__ __align__(16) float g_d2[BB * NN * MM];     // 64 MB squared distances
__device__ __align__(16) float g_w0[BB * NN * MM];     // 64 MB w0, overwritten by w
__device__ __align__(16) float g_match[BB * NN * MM];  // 64 MB accumulated match
__device__ float g_remainL[BB * NN];
__device__ float g_remainR[BB * MM];
__device__ float g_ratioL[BB * NN];
__device__ float g_ratioR[BB * MM];
__device__ float g_colsum[BB * MM];
__device__ float g_cost[BB];

// ---------------------------------------------------------------- init
__global__ void k_init() {
    int i = blockIdx.x * blockDim.x + threadIdx.x;
    if (i < BB * NN) g_remainL[i] = 1.0f;     // multiL = 1 (N == M)
    if (i < BB * MM) { g_remainR[i] = 1.0f; g_colsum[i] = 0.0f; }
    if (i < BB) g_cost[i] = 0.0f;
}

__global__ void k_zero_match() {
    size_t i = (size_t)blockIdx.x * blockDim.x + threadIdx.x;
    g_match[i] = 0.0f;
}

// ------------------------------------------- d2 (literal fp32 rounding)
__global__ void k_d2(const float* __restrict__ tm, const float* __restrict__ sr) {
    __shared__ alignas(16) float sx[MM];
    __shared__ alignas(16) float sy[MM];
    __shared__ alignas(16) float sz[MM];
    int b = blockIdx.y;
    const float* sb = sr + (size_t)b * MM * 3;
    for (int i = threadIdx.x; i < MM; i += blockDim.x) {
        sx[i] = sb[3 * i]; sy[i] = sb[3 * i + 1]; sz[i] = sb[3 * i + 2];
    }
    __syncthreads();
    int warp = threadIdx.x >> 5, lane = threadIdx.x & 31;
    int n = blockIdx.x * 8 + warp;
    size_t row = (size_t)(b * NN + n);
    const float* tp = tm + row * 3;
    float tx = tp[0], ty = tp[1], tz = tp[2];
    float* drow = g_d2 + row * MM;
#pragma unroll 4
    for (int it = 0; it < 16; ++it) {
        int m = it * 128 + lane * 4;
        float4 X = *(const float4*)(sx + m);
        float4 Y = *(const float4*)(sy + m);
        float4 Z = *(const float4*)(sz + m);
        float4 o;
        { float dx = __fadd_rn(tx, -X.x), dy = __fadd_rn(ty, -Y.x), dz = __fadd_rn(tz, -Z.x);
          o.x = __fadd_rn(__fadd_rn(__fmul_rn(dx, dx), __fmul_rn(dy, dy)), __fmul_rn(dz, dz)); }
        { float dx = __fadd_rn(tx, -X.y), dy = __fadd_rn(ty, -Y.y), dz = __fadd_rn(tz, -Z.y);
          o.y = __fadd_rn(__fadd_rn(__fmul_rn(dx, dx), __fmul_rn(dy, dy)), __fmul_rn(dz, dz)); }
        { float dx = __fadd_rn(tx, -X.z), dy = __fadd_rn(ty, -Y.z), dz = __fadd_rn(tz, -Z.z);
          o.z = __fadd_rn(__fadd_rn(__fmul_rn(dx, dx), __fmul_rn(dy, dy)), __fmul_rn(dz, dz)); }
        { float dx = __fadd_rn(tx, -X.w), dy = __fadd_rn(ty, -Y.w), dz = __fadd_rn(tz, -Z.w);
          o.w = __fadd_rn(__fadd_rn(__fmul_rn(dx, dx), __fmul_rn(dy, dy)), __fmul_rn(dz, dz)); }
        *(float4*)(drow + m) = o;
    }
}

// ------------------- w0 = expf(level*d2); suml; ratioL (one warp/row)
__global__ void kW(float level) {
    __shared__ alignas(16) float s_rm[MM];
    int b = blockIdx.y;
    for (int i = threadIdx.x; i < MM; i += blockDim.x) s_rm[i] = g_remainR[b * MM + i];
    __syncthreads();
    int warp = threadIdx.x >> 5, lane = threadIdx.x & 31;
    int n = blockIdx.x * 8 + warp;
    size_t row = (size_t)(b * NN + n);
    const float* drow = g_d2 + row * MM;
    float* wrow = g_w0 + row * MM;
    float suml = 0.0f;
#pragma unroll 2
    for (int it = 0; it < 16; ++it) {
        int m = it * 128 + lane * 4;
        float4 d4 = *(const float4*)(drow + m);
        float4 w;
        w.x = expf(__fmul_rn(level, d4.x));
        w.y = expf(__fmul_rn(level, d4.y));
        w.z = expf(__fmul_rn(level, d4.z));
        w.w = expf(__fmul_rn(level, d4.w));
        *(float4*)(wrow + m) = w;
        float4 rm = *(const float4*)(s_rm + m);
        suml = fmaf(w.x, rm.x, suml); suml = fmaf(w.y, rm.y, suml);
        suml = fmaf(w.z, rm.z, suml); suml = fmaf(w.w, rm.w, suml);
    }
#pragma unroll
    for (int o = 16; o; o >>= 1) suml += __shfl_xor_sync(0xffffffffu, suml, o);
    if (lane == 0) g_ratioL[row] = g_remainL[row] / (suml + 1e-9f);
}

// -------------------------- column reduce: colsum[m] += sum_n w0*ratioL
__global__ void kP2() {
    __shared__ float s_rl[64];
    int b = blockIdx.z, mt = blockIdx.y, nc = blockIdx.x;
    int t = threadIdx.x;
    if (t < 64) s_rl[t] = g_ratioL[b * NN + nc * 64 + t];
    __syncthreads();
    int m = mt * 1024 + t * 4;
    const float* base = g_w0 + ((size_t)(b * NN + nc * 64)) * MM + m;
    float a0 = 0, a1 = 0, a2 = 0, a3 = 0;
#pragma unroll 4
    for (int i = 0; i < 64; ++i) {
        float4 w = *(const float4*)(base + (size_t)i * MM);
        float rl = s_rl[i];
        a0 = fmaf(w.x, rl, a0); a1 = fmaf(w.y, rl, a1);
        a2 = fmaf(w.z, rl, a2); a3 = fmaf(w.w, rl, a3);
    }
    float* sp = &g_colsum[b * MM + m];
    atomicAdd(sp, a0); atomicAdd(sp + 1, a1);
    atomicAdd(sp + 2, a2); atomicAdd(sp + 3, a3);
}

// ----------------------------- ratioR = remainR/(sumr+1e-9); reset sums
__global__ void kC() {
    int i = blockIdx.x * blockDim.x + threadIdx.x;
    if (i >= BB * MM) return;
    g_ratioR[i] = g_remainR[i] / (g_colsum[i] + 1e-9f);
    g_colsum[i] = 0.0f;
}

// ------- w = (w0*ratioL)*ratioR; match += w; remainL -= rowsum(w) (clamped)
__global__ void kU() {
    __shared__ alignas(16) float s_rr[MM];
    int b = blockIdx.y;
    for (int i = threadIdx.x; i < MM; i += blockDim.x) s_rr[i] = g_ratioR[b * MM + i];
    __syncthreads();
    int warp = threadIdx.x >> 5, lane = threadIdx.x & 31;
    int n = blockIdx.x * 8 + warp;
    size_t row = (size_t)(b * NN + n);
    float rl = g_ratioL[row];
    float* wrow = g_w0 + row * MM;
    float* mrow = g_match + row * MM;
    float rowsum = 0.0f;
#pragma unroll 2
    for (int it = 0; it < 16; ++it) {
        int m = it * 128 + lane * 4;
        float4 w0 = *(const float4*)(wrow + m);
        float4 rr = *(const float4*)(s_rr + m);
        float4 w;
        w.x = __fmul_rn(__fmul_rn(w0.x, rl), rr.x);
        w.y = __fmul_rn(__fmul_rn(w0.y, rl), rr.y);
        w.z = __fmul_rn(__fmul_rn(w0.z, rl), rr.z);
        w.w = __fmul_rn(__fmul_rn(w0.w, rl), rr.w);
        *(float4*)(wrow + m) = w;                 // keep w for column pass
        float4 mt4 = *(const float4*)(mrow + m);
        mt4.x = __fadd_rn(mt4.x, w.x); mt4.y = __fadd_rn(mt4.y, w.y);
        mt4.z = __fadd_rn(mt4.z, w.z); mt4.w = __fadd_rn(mt4.w, w.w);
        *(float4*)(mrow + m) = mt4;
        rowsum = __fadd_rn(rowsum, __fadd_rn(__fadd_rn(w.x, w.y), __fadd_rn(w.z, w.w)));
    }
#pragma unroll
    for (int o = 16; o; o >>= 1) rowsum += __shfl_xor_sync(0xffffffffu, rowsum, o);
    if (lane == 0) g_remainL[row] = fmaxf(__fadd_rn(g_remainL[row], -rowsum), 0.0f);
}

// -------------------------------- column reduce of w: colsum[m] += sum_n w
__global__ void kQ2() {
    int b = blockIdx.z, mt = blockIdx.y, nc = blockIdx.x;
    int t = threadIdx.x;
    int m = mt * 1024 + t * 4;
    const float* base = g_w0 + ((size_t)(b * NN + nc * 64)) * MM + m;
    float a0 = 0, a1 = 0, a2 = 0, a3 = 0;
#pragma unroll 4
    for (int i = 0; i < 64; ++i) {
        float4 w = *(const float4*)(base + (size_t)i * MM);
        a0 += w.x; a1 += w.y; a2 += w.z; a3 += w.w;
    }
    float* sp = &g_colsum[b * MM + m];
    atomicAdd(sp, a0); atomicAdd(sp + 1, a1);
    atomicAdd(sp + 2, a2); atomicAdd(sp + 3, a3);
}

// ------------------------ remainR = max(remainR - colsum, 0); reset sums
__global__ void kR() {
    int i = blockIdx.x * blockDim.x + threadIdx.x;
    if (i >= BB * MM) return;
    g_remainR[i] = fmaxf(__fadd_rn(g_remainR[i], -g_colsum[i]), 0.0f);
    g_colsum[i] = 0.0f;
}

// ----------------------- cost_b = sum_{n,m} match * sqrt(max(d2,1e-24))
__global__ void k_cost() {
    __shared__ float s_cost[8];
    int b = blockIdx.y;
    int warp = threadIdx.x >> 5, lane = threadIdx.x & 31;
    int n = blockIdx.x * 8 + warp;
    size_t row = (size_t)(b * NN + n);
    const float* drow = g_d2 + row * MM;
    const float* mrow = g_match + row * MM;
    float acc = 0.0f;
#pragma unroll 4
    for (int it = 0; it < 16; ++it) {
        int m = it * 128 + lane * 4;
        float4 d4 = *(const float4*)(drow + m);
        float4 mt4 = *(const float4*)(mrow + m);
        acc = fmaf(mt4.x, sqrtf(fmaxf(d4.x, 1e-24f)), acc);
        acc = fmaf(mt4.y, sqrtf(fmaxf(d4.y, 1e-24f)), acc);
        acc = fmaf(mt4.z, sqrtf(fmaxf(d4.z, 1e-24f)), acc);
        acc = fmaf(mt4.w, sqrtf(fmaxf(d4.w, 1e-24f)), acc);
    }
#pragma unroll
    for (int o = 16; o; o >>= 1) acc += __shfl_xor_sync(0xffffffffu, acc, o);
    if (lane == 0) s_cost[warp] = acc;
    __syncthreads();
    if (threadIdx.x == 0) {
        float c = 0.0f;
#pragma unroll
        for (int w = 0; w < 8; ++w) c += s_cost[w];
        atomicAdd(&g_cost[b], c);
    }
}

__global__ void k_out(float* out) {
    out[0] = (g_cost[0] + g_cost[1] + g_cost[2] + g_cost[3]) * (1.0f / (BB * NN));
}

// ---------------------------------------------------------------- host
extern "C" void kernel_launch(void* const* d_in, const int* in_sizes, int n_in,
                              void* d_out, int out_size) {
    const float* tm = (const float*)d_in[0];
    const float* sr = (const float*)d_in[1];

    // levels: -4^7 .. -4^-1, then 0
    float kl[10];
    double lv = -16384.0;
    for (int j = 0; j < 8; ++j) { kl[j] = (float)lv; lv *= 0.25; }
    kl[8] = -0.25f;
    kl[9] = 0.0f;

    dim3 gA(256, BB);
    dim3 gP(32, 2, BB);
    k_init<<<16, 512>>>();
    k_zero_match<<<(BB * NN * MM) / 1024, 1024>>>();
    k_d2<<<gA, 256>>>(tm, sr);
    for (int j = 0; j < 10; ++j) {
        kW<<<gA, 256>>>(kl[j]);
        kP2<<<gP, 256>>>();
        kC<<<16, 512>>>();
        kU<<<gA, 256>>>();
        kQ2<<<gP, 256>>>();
        kR<<<16, 512>>>();
    }
    k_cost<<<gA, 256>>>();
    k_out<<<1, 1>>>((float*)d_out);
}